// round 14
// baseline (speedup 1.0000x reference)
#include <cuda_runtime.h>

#define HH 1024
#define WW 1024
#define NB 32
#define HW (HH*WW)

constexpr int TOX = 116;   // output tile width
constexpr int TOY = 84;    // output tile height
constexpr int RW  = 130;   // region cols (logical 0..129)
constexpr int RH  = 98;    // region rows (0..97)
constexpr int SPW = 136;   // smem row stride (floats)
constexpr int NW  = 12;    // warps
constexpr int NTH = 384;
constexpr int GX  = 9;     // ceil(1024/116)
constexpr int GY  = 13;    // ceil(1024/84)
constexpr int SMEMB = 2 * RH * SPW * 4;   // 106624 B -> 2 CTAs/SM

// ---- convA weights ----
#define A00 0.2538f
#define A01 0.5022f
#define A02 0.07344f
#define A10 0.17864f
#define A11 1.0622f
#define A12 0.24616f
#define A20 0.2454f
#define A21 0.90548f
#define A22 0.52616f
#define BIASX (-0.07002f)
// ---- convB weights ----
#define B00 (-0.083f)
#define B01 (-3.15852f)
#define B02 (3.24172f)
#define B10 (-2.0894f)
#define B11 (-9.34624f)
#define B12 (-2.0018f)
#define B20 (6.889f)
#define B21 (-1.53384f)
#define B22 (7.71856f)

constexpr double SUMA_D =
    0.2538 + 0.5022 + 0.07344 + 0.17864 + 1.0622 + 0.24616 +
    0.2454 + 0.90548 + 0.52616;
constexpr double SUMB_D =
    -0.083 - 3.15852 + 3.24172 - 2.0894 - 9.34624 - 2.0018 +
    6.889 - 1.53384 + 7.71856;
constexpr float K0C = (float)(0.5 * (1.0 - SUMA_D + (double)BIASX));
constexpr float S2K = (float)(0.5 * SUMA_D);     // convA(const 0.5 field)

// ---- scratch ----
__device__ float g_bu2[(size_t)NB * HW];
__device__ float g_sA[(size_t)NB * HW];
__device__ float g_sB[(size_t)NB * HW];
__device__ unsigned g_kmin, g_kmax;

__device__ __forceinline__ unsigned encf(float f) {
    unsigned b = __float_as_uint(f);
    return (b & 0x80000000u) ? ~b : (b | 0x80000000u);
}
__device__ __forceinline__ float decf(unsigned u) {
    return (u & 0x80000000u) ? __uint_as_float(u & 0x7FFFFFFFu)
                             : __uint_as_float(~u);
}

__global__ void k_init() { g_kmin = 0xFFFFFFFFu; g_kmax = 0u; }

__global__ void k_minmax(const float4* __restrict__ x, int n4) {
    float mn = 3.4e38f, mx = -3.4e38f;
    for (int i = blockIdx.x * blockDim.x + threadIdx.x; i < n4;
         i += gridDim.x * blockDim.x) {
        float4 v = x[i];
        mn = fminf(mn, fminf(fminf(v.x, v.y), fminf(v.z, v.w)));
        mx = fmaxf(mx, fmaxf(fmaxf(v.x, v.y), fmaxf(v.z, v.w)));
    }
#pragma unroll
    for (int o = 16; o; o >>= 1) {
        mn = fminf(mn, __shfl_xor_sync(0xFFFFFFFFu, mn, o));
        mx = fmaxf(mx, __shfl_xor_sync(0xFFFFFFFFu, mx, o));
    }
    __shared__ float smn[8], smx[8];
    int w = threadIdx.x >> 5, l = threadIdx.x & 31;
    if (!l) { smn[w] = mn; smx[w] = mx; }
    __syncthreads();
    if (!w) {
        mn = (l < 8) ? smn[l] : 3.4e38f;
        mx = (l < 8) ? smx[l] : -3.4e38f;
#pragma unroll
        for (int o = 4; o; o >>= 1) {
            mn = fminf(mn, __shfl_xor_sync(0xFFFFFFFFu, mn, o));
            mx = fmaxf(mx, __shfl_xor_sync(0xFFFFFFFFu, mx, o));
        }
        if (!l) {
            atomicMin(&g_kmin, encf(mn));
            atomicMax(&g_kmax, encf(mx));
        }
    }
}

struct R6 { float v0, v1, v2, v3, v4, v5; };

template <int K, int M>   // M=0: A weights, M=1: B weights
__device__ __forceinline__ void frow(const R6& r, float4& a) {
    constexpr float w0 = M ? ((K==0)?B00:(K==1)?B10:B20) : ((K==0)?A00:(K==1)?A10:A20);
    constexpr float w1 = M ? ((K==0)?B01:(K==1)?B11:B21) : ((K==0)?A01:(K==1)?A11:A21);
    constexpr float w2 = M ? ((K==0)?B02:(K==1)?B12:B22) : ((K==0)?A02:(K==1)?A12:A22);
    a.x = fmaf(r.v0, w0, a.x); a.x = fmaf(r.v1, w1, a.x); a.x = fmaf(r.v2, w2, a.x);
    a.y = fmaf(r.v1, w0, a.y); a.y = fmaf(r.v2, w1, a.y); a.y = fmaf(r.v3, w2, a.y);
    a.z = fmaf(r.v2, w0, a.z); a.z = fmaf(r.v3, w1, a.z); a.z = fmaf(r.v4, w2, a.z);
    a.w = fmaf(r.v3, w0, a.w); a.w = fmaf(r.v4, w1, a.w); a.w = fmaf(r.v5, w2, a.w);
}

// Final row-2 contribution with the clamp folded into the last FMA (sat).
#define SATFMA(acc, v)                                                    \
    asm("fma.rn.sat.f32 %0, %1, 0f3F06B26C, %0;" : "+f"(acc) : "f"(v))

__device__ __forceinline__ void frowZsat(const R6& r, float4& a) {
    a.x = fmaf(r.v0, A20, a.x); a.x = fmaf(r.v1, A21, a.x); SATFMA(a.x, r.v2);
    a.y = fmaf(r.v1, A20, a.y); a.y = fmaf(r.v2, A21, a.y); SATFMA(a.y, r.v3);
    a.z = fmaf(r.v2, A20, a.z); a.z = fmaf(r.v3, A21, a.z); SATFMA(a.z, r.v4);
    a.w = fmaf(r.v3, A20, a.w); a.w = fmaf(r.v4, A21, a.w); SATFMA(a.w, r.v5);
}

// BU2 = 0.5*convB(xn) + K0C ; 2 output rows per thread
__global__ void k_bu(const float* __restrict__ x) {
    int t = threadIdx.x;            // 0..255
    int y0 = blockIdx.y * 2;
    int img = blockIdx.z;
    int c0 = 4 * t;
    float mn = decf(g_kmin), mx = decf(g_kmax);
    float a2 = 2.0f / (mx - mn);
    float beta = fmaf(-mn, a2, -1.0f);
    const float* xi = x + (size_t)img * HW;
    float* bo = g_bu2 + (size_t)img * HW;

    bool interior = (t >= 1) & (t <= 254) & (y0 >= 2) & (y0 <= 1020);
    if (interior) {
        R6 r[4];
#pragma unroll
        for (int j = 0; j < 4; j++) {
            const float* rp = xi + (size_t)(y0 - 1 + j) * WW + c0;
            float4 m = __ldg((const float4*)rp);
            r[j].v0 = __ldg(rp - 1);
            r[j].v1 = m.x; r[j].v2 = m.y; r[j].v3 = m.z; r[j].v4 = m.w;
            r[j].v5 = __ldg(rp + 4);
        }
        float4 accT = make_float4(0.f, 0.f, 0.f, 0.f);
        float4 accB = make_float4(0.f, 0.f, 0.f, 0.f);
        frow<0, 1>(r[0], accT); frow<1, 1>(r[1], accT); frow<2, 1>(r[2], accT);
        frow<0, 1>(r[1], accB); frow<1, 1>(r[2], accB); frow<2, 1>(r[3], accB);
        float C2 = fmaf(0.5f * beta, (float)SUMB_D, K0C);
        float h = 0.5f * a2;
        *(float4*)(bo + (size_t)y0 * WW + c0) = make_float4(
            fmaf(h, accT.x, C2), fmaf(h, accT.y, C2),
            fmaf(h, accT.z, C2), fmaf(h, accT.w, C2));
        *(float4*)(bo + (size_t)(y0 + 1) * WW + c0) = make_float4(
            fmaf(h, accB.x, C2), fmaf(h, accB.y, C2),
            fmaf(h, accB.z, C2), fmaf(h, accB.w, C2));
    } else {
#pragma unroll
        for (int rr = 0; rr < 2; rr++) {
            int y = y0 + rr;
#pragma unroll
            for (int i = 0; i < 4; i++) {
                int gx = c0 + i;
                float acc = 0.f;
#define T(dy, dx, w)                                                   \
                {                                                      \
                    int yy = y + (dy), xx = gx + (dx);                 \
                    if ((unsigned)yy < HH && (unsigned)xx < WW) {      \
                        float xv = __ldg(xi + (size_t)yy * WW + xx);   \
                        acc = fmaf(fmaf(xv, a2, beta), (w), acc);      \
                    }                                                  \
                }
                T(-1, -1, B00) T(-1, 0, B01) T(-1, 1, B02)
                T( 0, -1, B10) T( 0, 0, B11) T( 0, 1, B12)
                T( 1, -1, B20) T( 1, 0, B21) T( 1, 1, B22)
#undef T
                bo[(size_t)y * WW + gx] = fmaf(acc, 0.5f, K0C);
            }
        }
    }
}

// Smem row fetch: one aligned LDS.128 + shuffles + boundary-lane patches.
__device__ __forceinline__ R6 ldrow(const float* p, int lane) {
    float4 m = *(const float4*)(p + 1);
    float lo = __shfl_up_sync(0xFFFFFFFFu, m.w, 1);
    float hi = __shfl_down_sync(0xFFFFFFFFu, m.x, 1);
    if (lane == 0)  lo = p[0];
    if (lane == 31) hi = p[5];
    R6 r; r.v0 = lo; r.v1 = m.x; r.v2 = m.y; r.v3 = m.z; r.v4 = m.w; r.v5 = hi;
    return r;
}

// Register-row halo assembly for the second substep (A already saturated).
__device__ __forceinline__ R6 finA(const float4& A) {
    R6 r;
    r.v0 = __shfl_up_sync(0xFFFFFFFFu, A.w, 1);
    r.v1 = A.x; r.v2 = A.y; r.v3 = A.z; r.v4 = A.w;
    r.v5 = __shfl_down_sync(0xFFFFFFFFu, A.x, 1);
    return r;
}
__device__ __forceinline__ R6 finA_e(const float4& A, bool yok,
                                     bool x0, bool x1, bool x2, bool x3) {
    float4 o;
    o.x = (yok && x0) ? A.x : 0.5f;
    o.y = (yok && x1) ? A.y : 0.5f;
    o.z = (yok && x2) ? A.z : 0.5f;
    o.w = (yok && x3) ? A.w : 0.5f;
    R6 r;
    r.v0 = __shfl_up_sync(0xFFFFFFFFu, o.w, 1);
    r.v1 = o.x; r.v2 = o.y; r.v3 = o.z; r.v4 = o.w;
    r.v5 = __shfl_down_sync(0xFFFFFFFFu, o.x, 1);
    return r;
}

template <bool EDGE>
__device__ __forceinline__ void emit4(float* q, const float4& A, bool yok,
                                      bool x0, bool x1, bool x2, bool x3) {
    float4 o;
    if (EDGE) {
        o.x = (yok && x0) ? A.x : 0.5f;
        o.y = (yok && x1) ? A.y : 0.5f;
        o.z = (yok && x2) ? A.z : 0.5f;
        o.w = (yok && x3) ? A.w : 0.5f;
    } else {
        o = A;
    }
    *(float4*)q = o;
}

// ---- double step: 2 CNN iterations per smem round-trip ----
// A-phase: rows o0-1..o0+8 of u_{t+1} in registers (12 smem row reads, clamped).
// B-phase: rows o0..o0+7 of u_{t+2}, consuming A rows via shuffle-halo; 8 stores.
template <bool EDGE>
__device__ __forceinline__ void dstep(const float* a, float* b,
        const float4* BU, const float* bug, int lane,
        int o0, int xb, int gx0, int gy0,
        bool x0, bool x1, bool x2, bool x3)
{
    const float* base = a + xb + 3;
    float* op = b + o0 * SPW + xb + 4;

    // BU2 for A rows o0-1 and o0+8 (from global; L2-resident)
    float4 BUm, BUp;
    if (!EDGE) {
        const float2* pm = (const float2*)(bug + (size_t)(gy0 + o0 - 1) * WW + (gx0 + 1 + xb));
        float2 u = __ldg(pm), v = __ldg(pm + 1);
        BUm = make_float4(u.x, u.y, v.x, v.y);
        const float2* pp = (const float2*)(bug + (size_t)(gy0 + o0 + 8) * WW + (gx0 + 1 + xb));
        u = __ldg(pp); v = __ldg(pp + 1);
        BUp = make_float4(u.x, u.y, v.x, v.y);
    } else {
        float vv[4];
        int gy = gy0 + o0 - 1;
#pragma unroll
        for (int i = 0; i < 4; i++) {
            int gx = gx0 + 1 + xb + i;
            vv[i] = ((unsigned)gy < HH && (unsigned)gx < WW)
                      ? __ldg(bug + (size_t)gy * WW + gx) : 0.f;
        }
        BUm = make_float4(vv[0], vv[1], vv[2], vv[3]);
        gy = gy0 + o0 + 8;
#pragma unroll
        for (int i = 0; i < 4; i++) {
            int gx = gx0 + 1 + xb + i;
            vv[i] = ((unsigned)gy < HH && (unsigned)gx < WW)
                      ? __ldg(bug + (size_t)gy * WW + gx) : 0.f;
        }
        BUp = make_float4(vv[0], vv[1], vv[2], vv[3]);
    }

    float4 A0, A1, A2, Q0, Q1, Q2;
    R6 s;

    // i=0: smem row o0-2 (clamped low for warp 0)
    s = ldrow(base + max(o0 - 2, 0) * SPW, lane);
    A0 = BUm; frow<0, 0>(s, A0);
    // i=1: row o0-1
    s = ldrow(base + (o0 - 1) * SPW, lane);
    frow<1, 0>(s, A0); A1 = BU[0]; frow<0, 0>(s, A1);
    // i=2: row o0 ; completes A row o0-1
    s = ldrow(base + o0 * SPW, lane);
    frowZsat(s, A0);
    frow<1, 0>(s, A1); A2 = BU[1]; frow<0, 0>(s, A2);
    {
        R6 rA = EDGE ? finA_e(A0, (unsigned)(gy0 + o0 - 1) < HH, x0, x1, x2, x3)
                     : finA(A0);
        Q1 = BU[0]; frow<0, 0>(rA, Q1);     // B row o0 init (Q1 = B idx 0)
    }
    A0 = A1; A1 = A2;

#pragma unroll
    for (int i = 3; i <= 11; i++) {
        int r = o0 - 2 + i;                         // o0+1 .. o0+9
        s = ldrow(base + min(r, RH - 1) * SPW, lane);
        frowZsat(s, A0);                            // completes A idx i-2 (row o0+i-3)
        if (i <= 10) frow<1, 0>(s, A1);
        if (i <= 9) { A2 = (i == 9) ? BUp : BU[i - 1]; frow<0, 0>(s, A2); }
        R6 rA = EDGE ? finA_e(A0, (unsigned)(gy0 + o0 + i - 3) < HH, x0, x1, x2, x3)
                     : finA(A0);
        if (i >= 4) {                               // completes B idx i-4 (row o0+i-4)
            frowZsat(rA, Q0);
            emit4<EDGE>(op + (i - 4) * SPW, Q0,
                        EDGE ? ((unsigned)(gy0 + o0 + i - 4) < HH) : true,
                        x0, x1, x2, x3);
        }
        if (i <= 10) frow<1, 0>(rA, Q1);            // B idx i-3
        if (i <= 9)  { Q2 = BU[i - 2]; frow<0, 0>(rA, Q2); }   // B idx i-2 init
        A0 = A1; A1 = A2;
        Q0 = Q1; Q1 = Q2;
    }
}

// single step (for the 7th step of passes 1,2)
template <bool EDGE>
__device__ __forceinline__ void sstep(const float* a, float* b,
        const float4* BU, int lane, int o0, int xb, int gy0,
        bool x0, bool x1, bool x2, bool x3)
{
    const float* ip = a + (o0 - 1) * SPW + xb + 3;
    float* op = b + o0 * SPW + xb + 4;
    float4 A0, A1, A2;
    R6 cur, nxt;
    cur = ldrow(ip, lane); ip += SPW;
    nxt = ldrow(ip, lane); ip += SPW;
    A0 = BU[0]; frow<0, 0>(cur, A0);
    cur = nxt;
    nxt = ldrow(ip, lane); ip += SPW;
    A1 = BU[1]; frow<1, 0>(cur, A0); frow<0, 0>(cur, A1);
#pragma unroll
    for (int k = 0; k < 6; k++) {
        cur = nxt;
        nxt = ldrow(ip, lane); ip += SPW;
        A2 = BU[2 + k];
        frowZsat(cur, A0);
        emit4<EDGE>(op + k * SPW, A0,
                    EDGE ? ((unsigned)(gy0 + o0 + k) < HH) : true,
                    x0, x1, x2, x3);
        frow<1, 0>(cur, A1); frow<0, 0>(cur, A2);
        A0 = A1; A1 = A2;
    }
    cur = nxt;
    nxt = ldrow(ip, lane);
    frowZsat(cur, A0);
    emit4<EDGE>(op + 6 * SPW, A0,
                EDGE ? ((unsigned)(gy0 + o0 + 6) < HH) : true, x0, x1, x2, x3);
    frow<1, 0>(cur, A1);
    frowZsat(nxt, A1);
    emit4<EDGE>(op + 7 * SPW, A1,
                EDGE ? ((unsigned)(gy0 + o0 + 7) < HH) : true, x0, x1, x2, x3);
}

// PASS 0: u1 analytic -> 3 double steps -> g_sA (u7)
// PASS 1: g_sA -> 3 double + 1 single -> g_sB (u14)
// PASS 2: g_sB -> 3 double + 1 single -> out  (u21)
template <int PASS>
__global__ void __launch_bounds__(NTH, 2) k_steps(float* __restrict__ out) {
    extern __shared__ float sm[];
    float* sA = sm;
    float* sB = sm + RH * SPW;
    const int tid = threadIdx.x, lane = tid & 31, wrp = tid >> 5;
    const int bx = blockIdx.x, by = blockIdx.y, img = blockIdx.z;
    const int gx0 = bx * TOX - 7, gy0 = by * TOY - 7;
    const bool edge = (bx == 0) | (bx == GX - 1) | (by == 0) | (by == GY - 1);

    const int o0 = 1 + 8 * wrp;
    const int xb = 4 * lane;
    const float* bsrc = g_bu2 + (size_t)img * HW;

    // ---- BU2 into registers (rows o0..o0+7) ----
    float4 BU[8];
    if (!edge) {
#pragma unroll
        for (int j = 0; j < 8; j++) {
            const float2* p = (const float2*)(bsrc +
                (size_t)(gy0 + o0 + j) * WW + (gx0 + 1 + xb));
            float2 u = __ldg(p), v = __ldg(p + 1);
            BU[j] = make_float4(u.x, u.y, v.x, v.y);
        }
    } else {
#pragma unroll
        for (int j = 0; j < 8; j++) {
            int gy = gy0 + o0 + j;
            float vv[4];
#pragma unroll
            for (int i = 0; i < 4; i++) {
                int gx = gx0 + 1 + xb + i;
                vv[i] = ((unsigned)gy < HH && (unsigned)gx < WW)
                          ? __ldg(bsrc + (size_t)gy * WW + gx) : 0.f;
            }
            BU[j] = make_float4(vv[0], vv[1], vv[2], vv[3]);
        }
    }

    // ---- source region into sA ----
    if (PASS == 0) {
        if (!edge) {
            for (int r = wrp; r < RH; r += NW) {
                const float* gp = bsrc + (size_t)(gy0 + r) * WW + gx0;
                float* sp = sA + r * SPW + 3;
                int c1 = 1 + 2 * lane, c2 = 65 + 2 * lane;
                float2 u = *(const float2*)(gp + c1);
                float2 v = *(const float2*)(gp + c2);
                u.x = __saturatef(S2K + u.x); u.y = __saturatef(S2K + u.y);
                v.x = __saturatef(S2K + v.x); v.y = __saturatef(S2K + v.y);
                *(float2*)(sp + c1) = u;
                *(float2*)(sp + c2) = v;
                if (lane == 0) {
                    sp[0]   = __saturatef(S2K + gp[0]);
                    sp[129] = __saturatef(S2K + gp[129]);
                }
            }
        } else {
            for (int r = wrp; r < RH; r += NW) {
                int gy = gy0 + r;
                bool yok = (unsigned)gy < HH;
                float* sp = sA + r * SPW + 3;
                for (int c = lane; c < RW; c += 32) {
                    int gx = gx0 + c;
                    sp[c] = (yok && (unsigned)gx < WW)
                              ? __saturatef(S2K + __ldg(bsrc + (size_t)gy * WW + gx))
                              : 0.5f;
                }
            }
        }
    } else {
        const float* src = (PASS == 1 ? g_sA : g_sB) + (size_t)img * HW;
        if (!edge) {
            for (int r = wrp; r < RH; r += NW) {
                const float* gp = src + (size_t)(gy0 + r) * WW + gx0;
                float* sp = sA + r * SPW + 3;
                int c1 = 1 + 2 * lane, c2 = 65 + 2 * lane;
                *(float2*)(sp + c1) = *(const float2*)(gp + c1);
                *(float2*)(sp + c2) = *(const float2*)(gp + c2);
                if (lane == 0) {
                    sp[0]   = gp[0];
                    sp[129] = gp[129];
                }
            }
        } else {
            for (int r = wrp; r < RH; r += NW) {
                int gy = gy0 + r;
                bool yok = (unsigned)gy < HH;
                float* sp = sA + r * SPW + 3;
                for (int c = lane; c < RW; c += 32) {
                    int gx = gx0 + c;
                    sp[c] = (yok && (unsigned)gx < WW)
                              ? __ldg(src + (size_t)gy * WW + gx) : 0.5f;
                }
            }
        }
    }
    __syncthreads();

    const bool x0 = (unsigned)(gx0 + xb + 1) < WW;
    const bool x1 = (unsigned)(gx0 + xb + 2) < WW;
    const bool x2 = (unsigned)(gx0 + xb + 3) < WW;
    const bool x3 = (unsigned)(gx0 + xb + 4) < WW;

    float* pa = sA;
    float* pb = sB;
#pragma unroll 1
    for (int d = 0; d < 3; d++) {
        if (edge) dstep<true >(pa, pb, BU, bsrc, lane, o0, xb, gx0, gy0, x0, x1, x2, x3);
        else      dstep<false>(pa, pb, BU, bsrc, lane, o0, xb, gx0, gy0, true, true, true, true);
        __syncthreads();
        float* t = pa; pa = pb; pb = t;
    }
    if (PASS != 0) {
        if (edge) sstep<true >(pa, pb, BU, lane, o0, xb, gy0, x0, x1, x2, x3);
        else      sstep<false>(pa, pb, BU, lane, o0, xb, gy0, true, true, true, true);
        __syncthreads();
        float* t = pa; pa = pb; pb = t;
    }
    float* fin = pa;

    // ---- writeback logical rows [7,90], cols [7,122] ----
    float* dst = (PASS == 0 ? g_sA : PASS == 1 ? g_sB : out) + (size_t)img * HW;
    if (!edge) {
        for (int r = 7 + wrp; r < 7 + TOY; r += NW) {
            float4* dp = (float4*)(dst + (size_t)(gy0 + r) * WW + gx0 + 7);
            const float* srow = fin + r * SPW + 10;
            if (lane < 29) {
                int c = 4 * lane;
                dp[lane] = make_float4(srow[c], srow[c+1], srow[c+2], srow[c+3]);
            }
        }
    } else {
        for (int r = 7 + wrp; r < 7 + TOY; r += NW) {
            int gy = gy0 + r;
            if ((unsigned)gy >= HH) continue;
            const float* srow = fin + r * SPW + 3;
            for (int c = 7 + lane; c < 7 + TOX; c += 32) {
                int gx = gx0 + c;
                if ((unsigned)gx < WW) dst[(size_t)gy * WW + gx] = srow[c];
            }
        }
    }
}

extern "C" void kernel_launch(void* const* d_in, const int* in_sizes, int n_in,
                              void* d_out, int out_size) {
    const float* x = (const float*)d_in[0];
    float* out = (float*)d_out;

    cudaFuncSetAttribute(k_steps<0>, cudaFuncAttributeMaxDynamicSharedMemorySize, SMEMB);
    cudaFuncSetAttribute(k_steps<1>, cudaFuncAttributeMaxDynamicSharedMemorySize, SMEMB);
    cudaFuncSetAttribute(k_steps<2>, cudaFuncAttributeMaxDynamicSharedMemorySize, SMEMB);

    k_init<<<1, 1>>>();
    k_minmax<<<2048, 256>>>((const float4*)x, (NB * HW) / 4);
    k_bu<<<dim3(1, HH / 2, NB), 256>>>(x);

    dim3 g(GX, GY, NB);
    k_steps<0><<<g, NTH, SMEMB>>>(out);
    k_steps<1><<<g, NTH, SMEMB>>>(out);
    k_steps<2><<<g, NTH, SMEMB>>>(out);
}

// round 15
// speedup vs baseline: 1.0102x; 1.0102x over previous
#include <cuda_runtime.h>

#define HH 1024
#define WW 1024
#define NB 32
#define HW (HH*WW)

constexpr int TOX = 116;   // output tile width
constexpr int TOY = 84;    // output tile height
constexpr int RW  = 130;   // region cols (logical 0..129)
constexpr int RH  = 98;    // region rows (0..97)
constexpr int SPW = 136;   // smem row stride (floats)
constexpr int NW  = 12;    // warps
constexpr int NTH = 384;
constexpr int GX  = 9;     // ceil(1024/116)
constexpr int GY  = 13;    // ceil(1024/84)
constexpr int SMEMB = 2 * RH * SPW * 4;   // 106624 B -> 2 CTAs/SM

// ---- convA weights ----
#define A00 0.2538f
#define A01 0.5022f
#define A02 0.07344f
#define A10 0.17864f
#define A11 1.0622f
#define A12 0.24616f
#define A20 0.2454f
#define A21 0.90548f
#define A22 0.52616f
#define BIASX (-0.07002f)
// ---- convB weights ----
#define B00 (-0.083f)
#define B01 (-3.15852f)
#define B02 (3.24172f)
#define B10 (-2.0894f)
#define B11 (-9.34624f)
#define B12 (-2.0018f)
#define B20 (6.889f)
#define B21 (-1.53384f)
#define B22 (7.71856f)

constexpr double SUMA_D =
    0.2538 + 0.5022 + 0.07344 + 0.17864 + 1.0622 + 0.24616 +
    0.2454 + 0.90548 + 0.52616;
constexpr double SUMB_D =
    -0.083 - 3.15852 + 3.24172 - 2.0894 - 9.34624 - 2.0018 +
    6.889 - 1.53384 + 7.71856;
constexpr float K0C = (float)(0.5 * (1.0 - SUMA_D + (double)BIASX));
constexpr float S2K = (float)(0.5 * SUMA_D);     // convA(const 0.5 field)

// ---- scratch ----
__device__ float g_bu2[(size_t)NB * HW];
__device__ float g_sA[(size_t)NB * HW];
__device__ float g_sB[(size_t)NB * HW];
__device__ unsigned g_kmin, g_kmax;

__device__ __forceinline__ unsigned encf(float f) {
    unsigned b = __float_as_uint(f);
    return (b & 0x80000000u) ? ~b : (b | 0x80000000u);
}
__device__ __forceinline__ float decf(unsigned u) {
    return (u & 0x80000000u) ? __uint_as_float(u & 0x7FFFFFFFu)
                             : __uint_as_float(~u);
}

__global__ void k_init() { g_kmin = 0xFFFFFFFFu; g_kmax = 0u; }

__global__ void k_minmax(const float4* __restrict__ x, int n4) {
    float mn = 3.4e38f, mx = -3.4e38f;
    for (int i = blockIdx.x * blockDim.x + threadIdx.x; i < n4;
         i += gridDim.x * blockDim.x) {
        float4 v = x[i];
        mn = fminf(mn, fminf(fminf(v.x, v.y), fminf(v.z, v.w)));
        mx = fmaxf(mx, fmaxf(fmaxf(v.x, v.y), fmaxf(v.z, v.w)));
    }
#pragma unroll
    for (int o = 16; o; o >>= 1) {
        mn = fminf(mn, __shfl_xor_sync(0xFFFFFFFFu, mn, o));
        mx = fmaxf(mx, __shfl_xor_sync(0xFFFFFFFFu, mx, o));
    }
    __shared__ float smn[8], smx[8];
    int w = threadIdx.x >> 5, l = threadIdx.x & 31;
    if (!l) { smn[w] = mn; smx[w] = mx; }
    __syncthreads();
    if (!w) {
        mn = (l < 8) ? smn[l] : 3.4e38f;
        mx = (l < 8) ? smx[l] : -3.4e38f;
#pragma unroll
        for (int o = 4; o; o >>= 1) {
            mn = fminf(mn, __shfl_xor_sync(0xFFFFFFFFu, mn, o));
            mx = fmaxf(mx, __shfl_xor_sync(0xFFFFFFFFu, mx, o));
        }
        if (!l) {
            atomicMin(&g_kmin, encf(mn));
            atomicMax(&g_kmax, encf(mx));
        }
    }
}

struct R6 { float v0, v1, v2, v3, v4, v5; };

template <int K, int M>   // M=0: A weights, M=1: B weights
__device__ __forceinline__ void frow(const R6& r, float4& a) {
    constexpr float w0 = M ? ((K==0)?B00:(K==1)?B10:B20) : ((K==0)?A00:(K==1)?A10:A20);
    constexpr float w1 = M ? ((K==0)?B01:(K==1)?B11:B21) : ((K==0)?A01:(K==1)?A11:A21);
    constexpr float w2 = M ? ((K==0)?B02:(K==1)?B12:B22) : ((K==0)?A02:(K==1)?A12:A22);
    a.x = fmaf(r.v0, w0, a.x); a.x = fmaf(r.v1, w1, a.x); a.x = fmaf(r.v2, w2, a.x);
    a.y = fmaf(r.v1, w0, a.y); a.y = fmaf(r.v2, w1, a.y); a.y = fmaf(r.v3, w2, a.y);
    a.z = fmaf(r.v2, w0, a.z); a.z = fmaf(r.v3, w1, a.z); a.z = fmaf(r.v4, w2, a.z);
    a.w = fmaf(r.v3, w0, a.w); a.w = fmaf(r.v4, w1, a.w); a.w = fmaf(r.v5, w2, a.w);
}

// Final row-2 contribution with the clamp folded into the last FMA (sat).
#define SATFMA(acc, v)                                                    \
    asm("fma.rn.sat.f32 %0, %1, 0f3F06B26C, %0;" : "+f"(acc) : "f"(v))

__device__ __forceinline__ void frowZsat(const R6& r, float4& a) {
    a.x = fmaf(r.v0, A20, a.x); a.x = fmaf(r.v1, A21, a.x); SATFMA(a.x, r.v2);
    a.y = fmaf(r.v1, A20, a.y); a.y = fmaf(r.v2, A21, a.y); SATFMA(a.y, r.v3);
    a.z = fmaf(r.v2, A20, a.z); a.z = fmaf(r.v3, A21, a.z); SATFMA(a.z, r.v4);
    a.w = fmaf(r.v3, A20, a.w); a.w = fmaf(r.v4, A21, a.w); SATFMA(a.w, r.v5);
}

// BU2 = 0.5*convB(xn) + K0C ; 2 output rows per thread
__global__ void k_bu(const float* __restrict__ x) {
    int t = threadIdx.x;            // 0..255
    int y0 = blockIdx.y * 2;
    int img = blockIdx.z;
    int c0 = 4 * t;
    float mn = decf(g_kmin), mx = decf(g_kmax);
    float a2 = 2.0f / (mx - mn);
    float beta = fmaf(-mn, a2, -1.0f);
    const float* xi = x + (size_t)img * HW;
    float* bo = g_bu2 + (size_t)img * HW;

    bool interior = (t >= 1) & (t <= 254) & (y0 >= 2) & (y0 <= 1020);
    if (interior) {
        R6 r[4];
#pragma unroll
        for (int j = 0; j < 4; j++) {
            const float* rp = xi + (size_t)(y0 - 1 + j) * WW + c0;
            float4 m = __ldg((const float4*)rp);
            r[j].v0 = __ldg(rp - 1);
            r[j].v1 = m.x; r[j].v2 = m.y; r[j].v3 = m.z; r[j].v4 = m.w;
            r[j].v5 = __ldg(rp + 4);
        }
        float4 accT = make_float4(0.f, 0.f, 0.f, 0.f);
        float4 accB = make_float4(0.f, 0.f, 0.f, 0.f);
        frow<0, 1>(r[0], accT); frow<1, 1>(r[1], accT); frow<2, 1>(r[2], accT);
        frow<0, 1>(r[1], accB); frow<1, 1>(r[2], accB); frow<2, 1>(r[3], accB);
        float C2 = fmaf(0.5f * beta, (float)SUMB_D, K0C);
        float h = 0.5f * a2;
        *(float4*)(bo + (size_t)y0 * WW + c0) = make_float4(
            fmaf(h, accT.x, C2), fmaf(h, accT.y, C2),
            fmaf(h, accT.z, C2), fmaf(h, accT.w, C2));
        *(float4*)(bo + (size_t)(y0 + 1) * WW + c0) = make_float4(
            fmaf(h, accB.x, C2), fmaf(h, accB.y, C2),
            fmaf(h, accB.z, C2), fmaf(h, accB.w, C2));
    } else {
#pragma unroll
        for (int rr = 0; rr < 2; rr++) {
            int y = y0 + rr;
#pragma unroll
            for (int i = 0; i < 4; i++) {
                int gx = c0 + i;
                float acc = 0.f;
#define T(dy, dx, w)                                                   \
                {                                                      \
                    int yy = y + (dy), xx = gx + (dx);                 \
                    if ((unsigned)yy < HH && (unsigned)xx < WW) {      \
                        float xv = __ldg(xi + (size_t)yy * WW + xx);   \
                        acc = fmaf(fmaf(xv, a2, beta), (w), acc);      \
                    }                                                  \
                }
                T(-1, -1, B00) T(-1, 0, B01) T(-1, 1, B02)
                T( 0, -1, B10) T( 0, 0, B11) T( 0, 1, B12)
                T( 1, -1, B20) T( 1, 0, B21) T( 1, 1, B22)
#undef T
                bo[(size_t)y * WW + gx] = fmaf(acc, 0.5f, K0C);
            }
        }
    }
}

// Smem row fetch: one aligned LDS.128 + shuffles + boundary-lane patches.
__device__ __forceinline__ R6 ldrow(const float* p, int lane) {
    float4 m = *(const float4*)(p + 1);
    float lo = __shfl_up_sync(0xFFFFFFFFu, m.w, 1);
    float hi = __shfl_down_sync(0xFFFFFFFFu, m.x, 1);
    if (lane == 0)  lo = p[0];
    if (lane == 31) hi = p[5];
    R6 r; r.v0 = lo; r.v1 = m.x; r.v2 = m.y; r.v3 = m.z; r.v4 = m.w; r.v5 = hi;
    return r;
}

// Register-row halo assembly for the second substep (A already saturated).
__device__ __forceinline__ R6 finA(const float4& A) {
    R6 r;
    r.v0 = __shfl_up_sync(0xFFFFFFFFu, A.w, 1);
    r.v1 = A.x; r.v2 = A.y; r.v3 = A.z; r.v4 = A.w;
    r.v5 = __shfl_down_sync(0xFFFFFFFFu, A.x, 1);
    return r;
}
__device__ __forceinline__ R6 finA_e(const float4& A, bool yok,
                                     bool x0, bool x1, bool x2, bool x3) {
    float4 o;
    o.x = (yok && x0) ? A.x : 0.5f;
    o.y = (yok && x1) ? A.y : 0.5f;
    o.z = (yok && x2) ? A.z : 0.5f;
    o.w = (yok && x3) ? A.w : 0.5f;
    R6 r;
    r.v0 = __shfl_up_sync(0xFFFFFFFFu, o.w, 1);
    r.v1 = o.x; r.v2 = o.y; r.v3 = o.z; r.v4 = o.w;
    r.v5 = __shfl_down_sync(0xFFFFFFFFu, o.x, 1);
    return r;
}

template <bool EDGE>
__device__ __forceinline__ void emit4(float* q, const float4& A, bool yok,
                                      bool x0, bool x1, bool x2, bool x3) {
    float4 o;
    if (EDGE) {
        o.x = (yok && x0) ? A.x : 0.5f;
        o.y = (yok && x1) ? A.y : 0.5f;
        o.z = (yok && x2) ? A.z : 0.5f;
        o.w = (yok && x3) ? A.w : 0.5f;
    } else {
        o = A;
    }
    *(float4*)q = o;
}

// ---- double step: 2 CNN iterations per smem round-trip ----
// A-phase: rows o0-1..o0+8 of u_{t+1} in registers (12 smem row reads, clamped).
// B-phase: rows o0..o0+7 of u_{t+2}, consuming A rows via shuffle-halo; 8 stores.
template <bool EDGE>
__device__ __forceinline__ void dstep(const float* a, float* b,
        const float4* BU, const float* bug, int lane,
        int o0, int xb, int gx0, int gy0,
        bool x0, bool x1, bool x2, bool x3)
{
    const float* base = a + xb + 3;
    float* op = b + o0 * SPW + xb + 4;

    // BU2 for A rows o0-1 and o0+8 (from global; L2-resident)
    float4 BUm, BUp;
    if (!EDGE) {
        const float2* pm = (const float2*)(bug + (size_t)(gy0 + o0 - 1) * WW + (gx0 + 1 + xb));
        float2 u = __ldg(pm), v = __ldg(pm + 1);
        BUm = make_float4(u.x, u.y, v.x, v.y);
        const float2* pp = (const float2*)(bug + (size_t)(gy0 + o0 + 8) * WW + (gx0 + 1 + xb));
        u = __ldg(pp); v = __ldg(pp + 1);
        BUp = make_float4(u.x, u.y, v.x, v.y);
    } else {
        float vv[4];
        int gy = gy0 + o0 - 1;
#pragma unroll
        for (int i = 0; i < 4; i++) {
            int gx = gx0 + 1 + xb + i;
            vv[i] = ((unsigned)gy < HH && (unsigned)gx < WW)
                      ? __ldg(bug + (size_t)gy * WW + gx) : 0.f;
        }
        BUm = make_float4(vv[0], vv[1], vv[2], vv[3]);
        gy = gy0 + o0 + 8;
#pragma unroll
        for (int i = 0; i < 4; i++) {
            int gx = gx0 + 1 + xb + i;
            vv[i] = ((unsigned)gy < HH && (unsigned)gx < WW)
                      ? __ldg(bug + (size_t)gy * WW + gx) : 0.f;
        }
        BUp = make_float4(vv[0], vv[1], vv[2], vv[3]);
    }

    float4 A0, A1, A2, Q0, Q1, Q2;
    R6 s;

    // i=0: smem row o0-2 (clamped low for warp 0)
    s = ldrow(base + max(o0 - 2, 0) * SPW, lane);
    A0 = BUm; frow<0, 0>(s, A0);
    // i=1: row o0-1
    s = ldrow(base + (o0 - 1) * SPW, lane);
    frow<1, 0>(s, A0); A1 = BU[0]; frow<0, 0>(s, A1);
    // i=2: row o0 ; completes A row o0-1
    s = ldrow(base + o0 * SPW, lane);
    frowZsat(s, A0);
    frow<1, 0>(s, A1); A2 = BU[1]; frow<0, 0>(s, A2);
    {
        R6 rA = EDGE ? finA_e(A0, (unsigned)(gy0 + o0 - 1) < HH, x0, x1, x2, x3)
                     : finA(A0);
        Q1 = BU[0]; frow<0, 0>(rA, Q1);     // B row o0 init (Q1 = B idx 0)
    }
    A0 = A1; A1 = A2;

#pragma unroll
    for (int i = 3; i <= 11; i++) {
        int r = o0 - 2 + i;                         // o0+1 .. o0+9
        s = ldrow(base + min(r, RH - 1) * SPW, lane);
        frowZsat(s, A0);                            // completes A idx i-2 (row o0+i-3)
        if (i <= 10) frow<1, 0>(s, A1);
        if (i <= 9) { A2 = (i == 9) ? BUp : BU[i - 1]; frow<0, 0>(s, A2); }
        R6 rA = EDGE ? finA_e(A0, (unsigned)(gy0 + o0 + i - 3) < HH, x0, x1, x2, x3)
                     : finA(A0);
        if (i >= 4) {                               // completes B idx i-4 (row o0+i-4)
            frowZsat(rA, Q0);
            emit4<EDGE>(op + (i - 4) * SPW, Q0,
                        EDGE ? ((unsigned)(gy0 + o0 + i - 4) < HH) : true,
                        x0, x1, x2, x3);
        }
        if (i <= 10) frow<1, 0>(rA, Q1);            // B idx i-3
        if (i <= 9)  { Q2 = BU[i - 2]; frow<0, 0>(rA, Q2); }   // B idx i-2 init
        A0 = A1; A1 = A2;
        Q0 = Q1; Q1 = Q2;
    }
}

// single step (for the 7th step of passes 1,2)
template <bool EDGE>
__device__ __forceinline__ void sstep(const float* a, float* b,
        const float4* BU, int lane, int o0, int xb, int gy0,
        bool x0, bool x1, bool x2, bool x3)
{
    const float* ip = a + (o0 - 1) * SPW + xb + 3;
    float* op = b + o0 * SPW + xb + 4;
    float4 A0, A1, A2;
    R6 cur, nxt;
    cur = ldrow(ip, lane); ip += SPW;
    nxt = ldrow(ip, lane); ip += SPW;
    A0 = BU[0]; frow<0, 0>(cur, A0);
    cur = nxt;
    nxt = ldrow(ip, lane); ip += SPW;
    A1 = BU[1]; frow<1, 0>(cur, A0); frow<0, 0>(cur, A1);
#pragma unroll
    for (int k = 0; k < 6; k++) {
        cur = nxt;
        nxt = ldrow(ip, lane); ip += SPW;
        A2 = BU[2 + k];
        frowZsat(cur, A0);
        emit4<EDGE>(op + k * SPW, A0,
                    EDGE ? ((unsigned)(gy0 + o0 + k) < HH) : true,
                    x0, x1, x2, x3);
        frow<1, 0>(cur, A1); frow<0, 0>(cur, A2);
        A0 = A1; A1 = A2;
    }
    cur = nxt;
    nxt = ldrow(ip, lane);
    frowZsat(cur, A0);
    emit4<EDGE>(op + 6 * SPW, A0,
                EDGE ? ((unsigned)(gy0 + o0 + 6) < HH) : true, x0, x1, x2, x3);
    frow<1, 0>(cur, A1);
    frowZsat(nxt, A1);
    emit4<EDGE>(op + 7 * SPW, A1,
                EDGE ? ((unsigned)(gy0 + o0 + 7) < HH) : true, x0, x1, x2, x3);
}

// PASS 0: u1 analytic -> 3 double steps -> g_sA (u7)
// PASS 1: g_sA -> 3 double + 1 single -> g_sB (u14)
// PASS 2: g_sB -> 3 double + 1 single -> out  (u21)
template <int PASS>
__global__ void __launch_bounds__(NTH, 2) k_steps(float* __restrict__ out) {
    extern __shared__ float sm[];
    float* sA = sm;
    float* sB = sm + RH * SPW;
    const int tid = threadIdx.x, lane = tid & 31, wrp = tid >> 5;
    const int bx = blockIdx.x, by = blockIdx.y, img = blockIdx.z;
    const int gx0 = bx * TOX - 7, gy0 = by * TOY - 7;
    const bool edge = (bx == 0) | (bx == GX - 1) | (by == 0) | (by == GY - 1);

    const int o0 = 1 + 8 * wrp;
    const int xb = 4 * lane;
    const float* bsrc = g_bu2 + (size_t)img * HW;

    // ---- BU2 into registers (rows o0..o0+7) ----
    float4 BU[8];
    if (!edge) {
#pragma unroll
        for (int j = 0; j < 8; j++) {
            const float2* p = (const float2*)(bsrc +
                (size_t)(gy0 + o0 + j) * WW + (gx0 + 1 + xb));
            float2 u = __ldg(p), v = __ldg(p + 1);
            BU[j] = make_float4(u.x, u.y, v.x, v.y);
        }
    } else {
#pragma unroll
        for (int j = 0; j < 8; j++) {
            int gy = gy0 + o0 + j;
            float vv[4];
#pragma unroll
            for (int i = 0; i < 4; i++) {
                int gx = gx0 + 1 + xb + i;
                vv[i] = ((unsigned)gy < HH && (unsigned)gx < WW)
                          ? __ldg(bsrc + (size_t)gy * WW + gx) : 0.f;
            }
            BU[j] = make_float4(vv[0], vv[1], vv[2], vv[3]);
        }
    }

    // ---- source region into sA ----
    if (PASS == 0) {
        if (!edge) {
            for (int r = wrp; r < RH; r += NW) {
                const float* gp = bsrc + (size_t)(gy0 + r) * WW + gx0;
                float* sp = sA + r * SPW + 3;
                int c1 = 1 + 2 * lane, c2 = 65 + 2 * lane;
                float2 u = *(const float2*)(gp + c1);
                float2 v = *(const float2*)(gp + c2);
                u.x = __saturatef(S2K + u.x); u.y = __saturatef(S2K + u.y);
                v.x = __saturatef(S2K + v.x); v.y = __saturatef(S2K + v.y);
                *(float2*)(sp + c1) = u;
                *(float2*)(sp + c2) = v;
                if (lane == 0) {
                    sp[0]   = __saturatef(S2K + gp[0]);
                    sp[129] = __saturatef(S2K + gp[129]);
                }
            }
        } else {
            for (int r = wrp; r < RH; r += NW) {
                int gy = gy0 + r;
                bool yok = (unsigned)gy < HH;
                float* sp = sA + r * SPW + 3;
                for (int c = lane; c < RW; c += 32) {
                    int gx = gx0 + c;
                    sp[c] = (yok && (unsigned)gx < WW)
                              ? __saturatef(S2K + __ldg(bsrc + (size_t)gy * WW + gx))
                              : 0.5f;
                }
            }
        }
    } else {
        const float* src = (PASS == 1 ? g_sA : g_sB) + (size_t)img * HW;
        if (!edge) {
            for (int r = wrp; r < RH; r += NW) {
                const float* gp = src + (size_t)(gy0 + r) * WW + gx0;
                float* sp = sA + r * SPW + 3;
                int c1 = 1 + 2 * lane, c2 = 65 + 2 * lane;
                *(float2*)(sp + c1) = *(const float2*)(gp + c1);
                *(float2*)(sp + c2) = *(const float2*)(gp + c2);
                if (lane == 0) {
                    sp[0]   = gp[0];
                    sp[129] = gp[129];
                }
            }
        } else {
            for (int r = wrp; r < RH; r += NW) {
                int gy = gy0 + r;
                bool yok = (unsigned)gy < HH;
                float* sp = sA + r * SPW + 3;
                for (int c = lane; c < RW; c += 32) {
                    int gx = gx0 + c;
                    sp[c] = (yok && (unsigned)gx < WW)
                              ? __ldg(src + (size_t)gy * WW + gx) : 0.5f;
                }
            }
        }
    }
    __syncthreads();

    const bool x0 = (unsigned)(gx0 + xb + 1) < WW;
    const bool x1 = (unsigned)(gx0 + xb + 2) < WW;
    const bool x2 = (unsigned)(gx0 + xb + 3) < WW;
    const bool x3 = (unsigned)(gx0 + xb + 4) < WW;

    float* pa = sA;
    float* pb = sB;
#pragma unroll 1
    for (int d = 0; d < 3; d++) {
        if (edge) dstep<true >(pa, pb, BU, bsrc, lane, o0, xb, gx0, gy0, x0, x1, x2, x3);
        else      dstep<false>(pa, pb, BU, bsrc, lane, o0, xb, gx0, gy0, true, true, true, true);
        __syncthreads();
        float* t = pa; pa = pb; pb = t;
    }
    if (PASS != 0) {
        if (edge) sstep<true >(pa, pb, BU, lane, o0, xb, gy0, x0, x1, x2, x3);
        else      sstep<false>(pa, pb, BU, lane, o0, xb, gy0, true, true, true, true);
        __syncthreads();
        float* t = pa; pa = pb; pb = t;
    }
    float* fin = pa;

    // ---- writeback logical rows [7,90], cols [7,122] ----
    float* dst = (PASS == 0 ? g_sA : PASS == 1 ? g_sB : out) + (size_t)img * HW;
    if (!edge) {
        for (int r = 7 + wrp; r < 7 + TOY; r += NW) {
            float4* dp = (float4*)(dst + (size_t)(gy0 + r) * WW + gx0 + 7);
            const float* srow = fin + r * SPW + 10;
            if (lane < 29) {
                int c = 4 * lane;
                dp[lane] = make_float4(srow[c], srow[c+1], srow[c+2], srow[c+3]);
            }
        }
    } else {
        for (int r = 7 + wrp; r < 7 + TOY; r += NW) {
            int gy = gy0 + r;
            if ((unsigned)gy >= HH) continue;
            const float* srow = fin + r * SPW + 3;
            for (int c = 7 + lane; c < 7 + TOX; c += 32) {
                int gx = gx0 + c;
                if ((unsigned)gx < WW) dst[(size_t)gy * WW + gx] = srow[c];
            }
        }
    }
}

extern "C" void kernel_launch(void* const* d_in, const int* in_sizes, int n_in,
                              void* d_out, int out_size) {
    const float* x = (const float*)d_in[0];
    float* out = (float*)d_out;

    cudaFuncSetAttribute(k_steps<0>, cudaFuncAttributeMaxDynamicSharedMemorySize, SMEMB);
    cudaFuncSetAttribute(k_steps<1>, cudaFuncAttributeMaxDynamicSharedMemorySize, SMEMB);
    cudaFuncSetAttribute(k_steps<2>, cudaFuncAttributeMaxDynamicSharedMemorySize, SMEMB);

    k_init<<<1, 1>>>();
    k_minmax<<<2048, 256>>>((const float4*)x, (NB * HW) / 4);
    k_bu<<<dim3(1, HH / 2, NB), 256>>>(x);

    dim3 g(GX, GY, NB);
    k_steps<0><<<g, NTH, SMEMB>>>(out);
    k_steps<1><<<g, NTH, SMEMB>>>(out);
    k_steps<2><<<g, NTH, SMEMB>>>(out);
}

// round 16
// speedup vs baseline: 1.0693x; 1.0585x over previous
#include <cuda_runtime.h>

#define HH 1024
#define WW 1024
#define NB 32
#define HW (HH*WW)

constexpr int TOX = 116;   // output tile width
constexpr int TOY = 84;    // output tile height
constexpr int RW  = 130;   // region cols (logical 0..129)
constexpr int RH  = 98;    // region rows (0..97)
constexpr int SPW = 136;   // smem row stride (floats)
constexpr int NW  = 16;    // warps
constexpr int NTH = 512;
constexpr int RPW = 6;     // output rows per warp (16*6 = 96 = RH-2)
constexpr int GX  = 9;     // ceil(1024/116)
constexpr int GY  = 13;    // ceil(1024/84)
constexpr int SMEMB = 2 * RH * SPW * 4;   // 106624 B -> 2 CTAs/SM

// ---- convA weights ----
#define A00 0.2538f
#define A01 0.5022f
#define A02 0.07344f
#define A10 0.17864f
#define A11 1.0622f
#define A12 0.24616f
#define A20 0.2454f
#define A21 0.90548f
#define A22 0.52616f
#define BIASX (-0.07002f)
// ---- convB weights ----
#define B00 (-0.083f)
#define B01 (-3.15852f)
#define B02 (3.24172f)
#define B10 (-2.0894f)
#define B11 (-9.34624f)
#define B12 (-2.0018f)
#define B20 (6.889f)
#define B21 (-1.53384f)
#define B22 (7.71856f)

constexpr double SUMA_D =
    0.2538 + 0.5022 + 0.07344 + 0.17864 + 1.0622 + 0.24616 +
    0.2454 + 0.90548 + 0.52616;
constexpr double SUMB_D =
    -0.083 - 3.15852 + 3.24172 - 2.0894 - 9.34624 - 2.0018 +
    6.889 - 1.53384 + 7.71856;
constexpr float K0C = (float)(0.5 * (1.0 - SUMA_D + (double)BIASX));
constexpr float S2K = (float)(0.5 * SUMA_D);     // convA(const 0.5 field)

// ---- scratch ----
__device__ float g_bu2[(size_t)NB * HW];
__device__ float g_sA[(size_t)NB * HW];
__device__ float g_sB[(size_t)NB * HW];
__device__ unsigned g_kmin, g_kmax;

__device__ __forceinline__ unsigned encf(float f) {
    unsigned b = __float_as_uint(f);
    return (b & 0x80000000u) ? ~b : (b | 0x80000000u);
}
__device__ __forceinline__ float decf(unsigned u) {
    return (u & 0x80000000u) ? __uint_as_float(u & 0x7FFFFFFFu)
                             : __uint_as_float(~u);
}

__global__ void k_init() { g_kmin = 0xFFFFFFFFu; g_kmax = 0u; }

__global__ void k_minmax(const float4* __restrict__ x, int n4) {
    float mn = 3.4e38f, mx = -3.4e38f;
    for (int i = blockIdx.x * blockDim.x + threadIdx.x; i < n4;
         i += gridDim.x * blockDim.x) {
        float4 v = x[i];
        mn = fminf(mn, fminf(fminf(v.x, v.y), fminf(v.z, v.w)));
        mx = fmaxf(mx, fmaxf(fmaxf(v.x, v.y), fmaxf(v.z, v.w)));
    }
#pragma unroll
    for (int o = 16; o; o >>= 1) {
        mn = fminf(mn, __shfl_xor_sync(0xFFFFFFFFu, mn, o));
        mx = fmaxf(mx, __shfl_xor_sync(0xFFFFFFFFu, mx, o));
    }
    __shared__ float smn[8], smx[8];
    int w = threadIdx.x >> 5, l = threadIdx.x & 31;
    if (!l) { smn[w] = mn; smx[w] = mx; }
    __syncthreads();
    if (!w) {
        mn = (l < 8) ? smn[l] : 3.4e38f;
        mx = (l < 8) ? smx[l] : -3.4e38f;
#pragma unroll
        for (int o = 4; o; o >>= 1) {
            mn = fminf(mn, __shfl_xor_sync(0xFFFFFFFFu, mn, o));
            mx = fmaxf(mx, __shfl_xor_sync(0xFFFFFFFFu, mx, o));
        }
        if (!l) {
            atomicMin(&g_kmin, encf(mn));
            atomicMax(&g_kmax, encf(mx));
        }
    }
}

struct R6 { float v0, v1, v2, v3, v4, v5; };

template <int K, int M>   // M=0: A weights, M=1: B weights
__device__ __forceinline__ void frow(const R6& r, float4& a) {
    constexpr float w0 = M ? ((K==0)?B00:(K==1)?B10:B20) : ((K==0)?A00:(K==1)?A10:A20);
    constexpr float w1 = M ? ((K==0)?B01:(K==1)?B11:B21) : ((K==0)?A01:(K==1)?A11:A21);
    constexpr float w2 = M ? ((K==0)?B02:(K==1)?B12:B22) : ((K==0)?A02:(K==1)?A12:A22);
    a.x = fmaf(r.v0, w0, a.x); a.x = fmaf(r.v1, w1, a.x); a.x = fmaf(r.v2, w2, a.x);
    a.y = fmaf(r.v1, w0, a.y); a.y = fmaf(r.v2, w1, a.y); a.y = fmaf(r.v3, w2, a.y);
    a.z = fmaf(r.v2, w0, a.z); a.z = fmaf(r.v3, w1, a.z); a.z = fmaf(r.v4, w2, a.z);
    a.w = fmaf(r.v3, w0, a.w); a.w = fmaf(r.v4, w1, a.w); a.w = fmaf(r.v5, w2, a.w);
}

// Final row-2 contribution with the clamp folded into the last FMA (sat).
#define SATFMA(acc, v)                                                    \
    asm("fma.rn.sat.f32 %0, %1, 0f3F06B26C, %0;" : "+f"(acc) : "f"(v))

__device__ __forceinline__ void frowZsat(const R6& r, float4& a) {
    a.x = fmaf(r.v0, A20, a.x); a.x = fmaf(r.v1, A21, a.x); SATFMA(a.x, r.v2);
    a.y = fmaf(r.v1, A20, a.y); a.y = fmaf(r.v2, A21, a.y); SATFMA(a.y, r.v3);
    a.z = fmaf(r.v2, A20, a.z); a.z = fmaf(r.v3, A21, a.z); SATFMA(a.z, r.v4);
    a.w = fmaf(r.v3, A20, a.w); a.w = fmaf(r.v4, A21, a.w); SATFMA(a.w, r.v5);
}

// BU2 = 0.5*convB(xn) + K0C ; 2 output rows per thread
__global__ void k_bu(const float* __restrict__ x) {
    int t = threadIdx.x;            // 0..255
    int y0 = blockIdx.y * 2;
    int img = blockIdx.z;
    int c0 = 4 * t;
    float mn = decf(g_kmin), mx = decf(g_kmax);
    float a2 = 2.0f / (mx - mn);
    float beta = fmaf(-mn, a2, -1.0f);
    const float* xi = x + (size_t)img * HW;
    float* bo = g_bu2 + (size_t)img * HW;

    bool interior = (t >= 1) & (t <= 254) & (y0 >= 2) & (y0 <= 1020);
    if (interior) {
        R6 r[4];
#pragma unroll
        for (int j = 0; j < 4; j++) {
            const float* rp = xi + (size_t)(y0 - 1 + j) * WW + c0;
            float4 m = __ldg((const float4*)rp);
            r[j].v0 = __ldg(rp - 1);
            r[j].v1 = m.x; r[j].v2 = m.y; r[j].v3 = m.z; r[j].v4 = m.w;
            r[j].v5 = __ldg(rp + 4);
        }
        float4 accT = make_float4(0.f, 0.f, 0.f, 0.f);
        float4 accB = make_float4(0.f, 0.f, 0.f, 0.f);
        frow<0, 1>(r[0], accT); frow<1, 1>(r[1], accT); frow<2, 1>(r[2], accT);
        frow<0, 1>(r[1], accB); frow<1, 1>(r[2], accB); frow<2, 1>(r[3], accB);
        float C2 = fmaf(0.5f * beta, (float)SUMB_D, K0C);
        float h = 0.5f * a2;
        *(float4*)(bo + (size_t)y0 * WW + c0) = make_float4(
            fmaf(h, accT.x, C2), fmaf(h, accT.y, C2),
            fmaf(h, accT.z, C2), fmaf(h, accT.w, C2));
        *(float4*)(bo + (size_t)(y0 + 1) * WW + c0) = make_float4(
            fmaf(h, accB.x, C2), fmaf(h, accB.y, C2),
            fmaf(h, accB.z, C2), fmaf(h, accB.w, C2));
    } else {
#pragma unroll
        for (int rr = 0; rr < 2; rr++) {
            int y = y0 + rr;
#pragma unroll
            for (int i = 0; i < 4; i++) {
                int gx = c0 + i;
                float acc = 0.f;
#define T(dy, dx, w)                                                   \
                {                                                      \
                    int yy = y + (dy), xx = gx + (dx);                 \
                    if ((unsigned)yy < HH && (unsigned)xx < WW) {      \
                        float xv = __ldg(xi + (size_t)yy * WW + xx);   \
                        acc = fmaf(fmaf(xv, a2, beta), (w), acc);      \
                    }                                                  \
                }
                T(-1, -1, B00) T(-1, 0, B01) T(-1, 1, B02)
                T( 0, -1, B10) T( 0, 0, B11) T( 0, 1, B12)
                T( 1, -1, B20) T( 1, 0, B21) T( 1, 1, B22)
#undef T
                bo[(size_t)y * WW + gx] = fmaf(acc, 0.5f, K0C);
            }
        }
    }
}

// Smem row fetch: one aligned LDS.128 + shuffles + boundary-lane patches.
__device__ __forceinline__ R6 ldrow(const float* p, int lane) {
    float4 m = *(const float4*)(p + 1);
    float lo = __shfl_up_sync(0xFFFFFFFFu, m.w, 1);
    float hi = __shfl_down_sync(0xFFFFFFFFu, m.x, 1);
    if (lane == 0)  lo = p[0];
    if (lane == 31) hi = p[5];
    R6 r; r.v0 = lo; r.v1 = m.x; r.v2 = m.y; r.v3 = m.z; r.v4 = m.w; r.v5 = hi;
    return r;
}

// A is already saturated (frowZsat); edge tiles force padding value 0.5.
template <bool EDGE>
__device__ __forceinline__ void emit4(float* q, const float4& A, bool yok,
                                      bool x0, bool x1, bool x2, bool x3) {
    float4 o;
    if (EDGE) {
        o.x = (yok && x0) ? A.x : 0.5f;
        o.y = (yok && x1) ? A.y : 0.5f;
        o.z = (yok && x2) ? A.z : 0.5f;
        o.w = (yok && x3) ? A.w : 0.5f;
    } else {
        o = A;
    }
    *(float4*)q = o;
}

// Software-pipelined single step, 6 output rows per warp (8 row reads).
template <bool EDGE>
__device__ __forceinline__ float* do_steps(int nstep, float* a, float* b,
                                           const float4* BU, int lane,
                                           int o0, int xb, int gy0,
                                           bool x0, bool x1, bool x2, bool x3) {
#pragma unroll 1
    for (int t = 0; t < nstep; t++) {
        const float* ip = a + (o0 - 1) * SPW + xb + 3;
        float* op = b + o0 * SPW + xb + 4;
        float4 A0, A1, A2;
        R6 cur, nxt;
        cur = ldrow(ip, lane); ip += SPW;         // row o0-1
        nxt = ldrow(ip, lane); ip += SPW;         // row o0 (prefetched)
        A0 = BU[0]; frow<0, 0>(cur, A0);
        cur = nxt;
        nxt = ldrow(ip, lane); ip += SPW;         // prefetch row o0+1
        A1 = BU[1]; frow<1, 0>(cur, A0); frow<0, 0>(cur, A1);
#pragma unroll
        for (int k = 0; k < 4; k++) {             // consume rows o0+1 .. o0+4
            cur = nxt;
            nxt = ldrow(ip, lane); ip += SPW;     // prefetch rows o0+2 .. o0+5
            A2 = BU[2 + k];
            frowZsat(cur, A0);
            emit4<EDGE>(op + k * SPW, A0,
                        EDGE ? ((unsigned)(gy0 + o0 + k) < HH) : true,
                        x0, x1, x2, x3);
            frow<1, 0>(cur, A1); frow<0, 0>(cur, A2);
            A0 = A1; A1 = A2;
        }
        cur = nxt;
        nxt = ldrow(ip, lane);                    // prefetch row o0+6
        frowZsat(cur, A0);                        // consume row o0+5
        emit4<EDGE>(op + 4 * SPW, A0,
                    EDGE ? ((unsigned)(gy0 + o0 + 4) < HH) : true, x0, x1, x2, x3);
        frow<1, 0>(cur, A1);
        frowZsat(nxt, A1);                        // consume row o0+6
        emit4<EDGE>(op + 5 * SPW, A1,
                    EDGE ? ((unsigned)(gy0 + o0 + 5) < HH) : true, x0, x1, x2, x3);
        __syncthreads();
        float* tmp = a; a = b; b = tmp;
    }
    return a;   // final buffer
}

// PASS 0: u1 analytic -> 6 steps -> g_sA (u7)
// PASS 1: g_sA -> 7 steps -> g_sB (u14)
// PASS 2: g_sB -> 7 steps -> out  (u21)
template <int PASS>
__global__ void __launch_bounds__(NTH, 2) k_steps(float* __restrict__ out) {
    extern __shared__ float sm[];
    float* sA = sm;
    float* sB = sm + RH * SPW;
    const int tid = threadIdx.x, lane = tid & 31, wrp = tid >> 5;
    const int bx = blockIdx.x, by = blockIdx.y, img = blockIdx.z;
    const int gx0 = bx * TOX - 7, gy0 = by * TOY - 7;
    const bool edge = (bx == 0) | (bx == GX - 1) | (by == 0) | (by == GY - 1);

    const int o0 = 1 + RPW * wrp;   // update rows o0..o0+5 (1..96)
    const int xb = 4 * lane;        // update logical cols xb+1..xb+4 (1..128)
    const float* bsrc = g_bu2 + (size_t)img * HW;

    // ---- BU2 into registers (rows o0..o0+5) ----
    float4 BU[RPW];
    if (!edge) {
#pragma unroll
        for (int j = 0; j < RPW; j++) {
            const float2* p = (const float2*)(bsrc +
                (size_t)(gy0 + o0 + j) * WW + (gx0 + 1 + xb));
            float2 u = __ldg(p), v = __ldg(p + 1);
            BU[j] = make_float4(u.x, u.y, v.x, v.y);
        }
    } else {
#pragma unroll
        for (int j = 0; j < RPW; j++) {
            int gy = gy0 + o0 + j;
            float vv[4];
#pragma unroll
            for (int i = 0; i < 4; i++) {
                int gx = gx0 + 1 + xb + i;
                vv[i] = ((unsigned)gy < HH && (unsigned)gx < WW)
                          ? __ldg(bsrc + (size_t)gy * WW + gx) : 0.f;
            }
            BU[j] = make_float4(vv[0], vv[1], vv[2], vv[3]);
        }
    }

    // ---- source region into sA ----
    if (PASS == 0) {
        if (!edge) {
            for (int r = wrp; r < RH; r += NW) {
                const float* gp = bsrc + (size_t)(gy0 + r) * WW + gx0;
                float* sp = sA + r * SPW + 3;
                int c1 = 1 + 2 * lane, c2 = 65 + 2 * lane;
                float2 u = *(const float2*)(gp + c1);
                float2 v = *(const float2*)(gp + c2);
                u.x = __saturatef(S2K + u.x); u.y = __saturatef(S2K + u.y);
                v.x = __saturatef(S2K + v.x); v.y = __saturatef(S2K + v.y);
                *(float2*)(sp + c1) = u;
                *(float2*)(sp + c2) = v;
                if (lane == 0) {
                    sp[0]   = __saturatef(S2K + gp[0]);
                    sp[129] = __saturatef(S2K + gp[129]);
                }
            }
        } else {
            for (int r = wrp; r < RH; r += NW) {
                int gy = gy0 + r;
                bool yok = (unsigned)gy < HH;
                float* sp = sA + r * SPW + 3;
                for (int c = lane; c < RW; c += 32) {
                    int gx = gx0 + c;
                    sp[c] = (yok && (unsigned)gx < WW)
                              ? __saturatef(S2K + __ldg(bsrc + (size_t)gy * WW + gx))
                              : 0.5f;
                }
            }
        }
    } else {
        const float* src = (PASS == 1 ? g_sA : g_sB) + (size_t)img * HW;
        if (!edge) {
            for (int r = wrp; r < RH; r += NW) {
                const float* gp = src + (size_t)(gy0 + r) * WW + gx0;
                float* sp = sA + r * SPW + 3;
                int c1 = 1 + 2 * lane, c2 = 65 + 2 * lane;
                *(float2*)(sp + c1) = *(const float2*)(gp + c1);
                *(float2*)(sp + c2) = *(const float2*)(gp + c2);
                if (lane == 0) {
                    sp[0]   = gp[0];
                    sp[129] = gp[129];
                }
            }
        } else {
            for (int r = wrp; r < RH; r += NW) {
                int gy = gy0 + r;
                bool yok = (unsigned)gy < HH;
                float* sp = sA + r * SPW + 3;
                for (int c = lane; c < RW; c += 32) {
                    int gx = gx0 + c;
                    sp[c] = (yok && (unsigned)gx < WW)
                              ? __ldg(src + (size_t)gy * WW + gx) : 0.5f;
                }
            }
        }
    }
    __syncthreads();

    const bool x0 = (unsigned)(gx0 + xb + 1) < WW;
    const bool x1 = (unsigned)(gx0 + xb + 2) < WW;
    const bool x2 = (unsigned)(gx0 + xb + 3) < WW;
    const bool x3 = (unsigned)(gx0 + xb + 4) < WW;

    const int nstep = (PASS == 0) ? 6 : 7;
    float* fin = edge
        ? do_steps<true >(nstep, sA, sB, BU, lane, o0, xb, gy0, x0, x1, x2, x3)
        : do_steps<false>(nstep, sA, sB, BU, lane, o0, xb, gy0, true, true, true, true);

    // ---- writeback logical rows [7,90], cols [7,122] ----
    float* dst = (PASS == 0 ? g_sA : PASS == 1 ? g_sB : out) + (size_t)img * HW;
    if (!edge) {
        for (int r = 7 + wrp; r < 7 + TOY; r += NW) {
            float4* dp = (float4*)(dst + (size_t)(gy0 + r) * WW + gx0 + 7);
            const float* srow = fin + r * SPW + 10;   // logical col 7 -> phys 10
            if (lane < 29) {
                int c = 4 * lane;
                dp[lane] = make_float4(srow[c], srow[c+1], srow[c+2], srow[c+3]);
            }
        }
    } else {
        for (int r = 7 + wrp; r < 7 + TOY; r += NW) {
            int gy = gy0 + r;
            if ((unsigned)gy >= HH) continue;
            const float* srow = fin + r * SPW + 3;
            for (int c = 7 + lane; c < 7 + TOX; c += 32) {
                int gx = gx0 + c;
                if ((unsigned)gx < WW) dst[(size_t)gy * WW + gx] = srow[c];
            }
        }
    }
}

extern "C" void kernel_launch(void* const* d_in, const int* in_sizes, int n_in,
                              void* d_out, int out_size) {
    const float* x = (const float*)d_in[0];
    float* out = (float*)d_out;

    cudaFuncSetAttribute(k_steps<0>, cudaFuncAttributeMaxDynamicSharedMemorySize, SMEMB);
    cudaFuncSetAttribute(k_steps<1>, cudaFuncAttributeMaxDynamicSharedMemorySize, SMEMB);
    cudaFuncSetAttribute(k_steps<2>, cudaFuncAttributeMaxDynamicSharedMemorySize, SMEMB);

    k_init<<<1, 1>>>();
    k_minmax<<<2048, 256>>>((const float4*)x, (NB * HW) / 4);
    k_bu<<<dim3(1, HH / 2, NB), 256>>>(x);

    dim3 g(GX, GY, NB);
    k_steps<0><<<g, NTH, SMEMB>>>(out);
    k_steps<1><<<g, NTH, SMEMB>>>(out);
    k_steps<2><<<g, NTH, SMEMB>>>(out);
}

// round 17
// speedup vs baseline: 1.0915x; 1.0208x over previous
#include <cuda_runtime.h>

#define HH 1024
#define WW 1024
#define NB 32
#define HW (HH*WW)

constexpr int TOX = 116;   // output tile width
constexpr int TOY = 84;    // output tile height
constexpr int RW  = 130;   // region cols (logical 0..129)
constexpr int RH  = 98;    // region rows (0..97)
constexpr int SPW = 136;   // smem row stride (floats)
constexpr int NW  = 16;    // warps
constexpr int NTH = 512;
constexpr int RPW = 6;     // output rows per warp (16*6 = 96 = RH-2)
constexpr int GX  = 9;     // ceil(1024/116)
constexpr int GY  = 13;    // ceil(1024/84)
constexpr int SMEMB = 2 * RH * SPW * 4;   // 106624 B -> 2 CTAs/SM

// ---- convA weights ----
#define A00 0.2538f
#define A01 0.5022f
#define A02 0.07344f
#define A10 0.17864f
#define A11 1.0622f
#define A12 0.24616f
#define A20 0.2454f
#define A21 0.90548f
#define A22 0.52616f
#define BIASX (-0.07002f)
// ---- convB weights ----
#define B00 (-0.083f)
#define B01 (-3.15852f)
#define B02 (3.24172f)
#define B10 (-2.0894f)
#define B11 (-9.34624f)
#define B12 (-2.0018f)
#define B20 (6.889f)
#define B21 (-1.53384f)
#define B22 (7.71856f)

constexpr double SUMA_D =
    0.2538 + 0.5022 + 0.07344 + 0.17864 + 1.0622 + 0.24616 +
    0.2454 + 0.90548 + 0.52616;
constexpr double SUMB_D =
    -0.083 - 3.15852 + 3.24172 - 2.0894 - 9.34624 - 2.0018 +
    6.889 - 1.53384 + 7.71856;
constexpr float K0C = (float)(0.5 * (1.0 - SUMA_D + (double)BIASX));
constexpr float S2K = (float)(0.5 * SUMA_D);     // convA(const 0.5 field)

// ---- scratch ----
__device__ float g_bu2[(size_t)NB * HW];
__device__ float g_sA[(size_t)NB * HW];
__device__ float g_sB[(size_t)NB * HW];
__device__ unsigned g_kmin, g_kmax;

__device__ __forceinline__ unsigned encf(float f) {
    unsigned b = __float_as_uint(f);
    return (b & 0x80000000u) ? ~b : (b | 0x80000000u);
}
__device__ __forceinline__ float decf(unsigned u) {
    return (u & 0x80000000u) ? __uint_as_float(u & 0x7FFFFFFFu)
                             : __uint_as_float(~u);
}

__global__ void k_init() { g_kmin = 0xFFFFFFFFu; g_kmax = 0u; }

__global__ void k_minmax(const float4* __restrict__ x, int n4) {
    float mn = 3.4e38f, mx = -3.4e38f;
    for (int i = blockIdx.x * blockDim.x + threadIdx.x; i < n4;
         i += gridDim.x * blockDim.x) {
        float4 v = x[i];
        mn = fminf(mn, fminf(fminf(v.x, v.y), fminf(v.z, v.w)));
        mx = fmaxf(mx, fmaxf(fmaxf(v.x, v.y), fmaxf(v.z, v.w)));
    }
#pragma unroll
    for (int o = 16; o; o >>= 1) {
        mn = fminf(mn, __shfl_xor_sync(0xFFFFFFFFu, mn, o));
        mx = fmaxf(mx, __shfl_xor_sync(0xFFFFFFFFu, mx, o));
    }
    __shared__ float smn[8], smx[8];
    int w = threadIdx.x >> 5, l = threadIdx.x & 31;
    if (!l) { smn[w] = mn; smx[w] = mx; }
    __syncthreads();
    if (!w) {
        mn = (l < 8) ? smn[l] : 3.4e38f;
        mx = (l < 8) ? smx[l] : -3.4e38f;
#pragma unroll
        for (int o = 4; o; o >>= 1) {
            mn = fminf(mn, __shfl_xor_sync(0xFFFFFFFFu, mn, o));
            mx = fmaxf(mx, __shfl_xor_sync(0xFFFFFFFFu, mx, o));
        }
        if (!l) {
            atomicMin(&g_kmin, encf(mn));
            atomicMax(&g_kmax, encf(mx));
        }
    }
}

struct R6 { float v0, v1, v2, v3, v4, v5; };

template <int K, int M>   // M=0: A weights, M=1: B weights
__device__ __forceinline__ void frow(const R6& r, float4& a) {
    constexpr float w0 = M ? ((K==0)?B00:(K==1)?B10:B20) : ((K==0)?A00:(K==1)?A10:A20);
    constexpr float w1 = M ? ((K==0)?B01:(K==1)?B11:B21) : ((K==0)?A01:(K==1)?A11:A21);
    constexpr float w2 = M ? ((K==0)?B02:(K==1)?B12:B22) : ((K==0)?A02:(K==1)?A12:A22);
    a.x = fmaf(r.v0, w0, a.x); a.x = fmaf(r.v1, w1, a.x); a.x = fmaf(r.v2, w2, a.x);
    a.y = fmaf(r.v1, w0, a.y); a.y = fmaf(r.v2, w1, a.y); a.y = fmaf(r.v3, w2, a.y);
    a.z = fmaf(r.v2, w0, a.z); a.z = fmaf(r.v3, w1, a.z); a.z = fmaf(r.v4, w2, a.z);
    a.w = fmaf(r.v3, w0, a.w); a.w = fmaf(r.v4, w1, a.w); a.w = fmaf(r.v5, w2, a.w);
}

// Final row-2 contribution with the clamp folded into the last FMA (sat).
#define SATFMA(acc, v)                                                    \
    asm("fma.rn.sat.f32 %0, %1, 0f3F06B26C, %0;" : "+f"(acc) : "f"(v))

__device__ __forceinline__ void frowZsat(const R6& r, float4& a) {
    a.x = fmaf(r.v0, A20, a.x); a.x = fmaf(r.v1, A21, a.x); SATFMA(a.x, r.v2);
    a.y = fmaf(r.v1, A20, a.y); a.y = fmaf(r.v2, A21, a.y); SATFMA(a.y, r.v3);
    a.z = fmaf(r.v2, A20, a.z); a.z = fmaf(r.v3, A21, a.z); SATFMA(a.z, r.v4);
    a.w = fmaf(r.v3, A20, a.w); a.w = fmaf(r.v4, A21, a.w); SATFMA(a.w, r.v5);
}

// BU2 = 0.5*convB(xn) + K0C ; 2 output rows per thread
__global__ void k_bu(const float* __restrict__ x) {
    int t = threadIdx.x;            // 0..255
    int y0 = blockIdx.y * 2;
    int img = blockIdx.z;
    int c0 = 4 * t;
    float mn = decf(g_kmin), mx = decf(g_kmax);
    float a2 = 2.0f / (mx - mn);
    float beta = fmaf(-mn, a2, -1.0f);
    const float* xi = x + (size_t)img * HW;
    float* bo = g_bu2 + (size_t)img * HW;

    bool interior = (t >= 1) & (t <= 254) & (y0 >= 2) & (y0 <= 1020);
    if (interior) {
        R6 r[4];
#pragma unroll
        for (int j = 0; j < 4; j++) {
            const float* rp = xi + (size_t)(y0 - 1 + j) * WW + c0;
            float4 m = __ldg((const float4*)rp);
            r[j].v0 = __ldg(rp - 1);
            r[j].v1 = m.x; r[j].v2 = m.y; r[j].v3 = m.z; r[j].v4 = m.w;
            r[j].v5 = __ldg(rp + 4);
        }
        float4 accT = make_float4(0.f, 0.f, 0.f, 0.f);
        float4 accB = make_float4(0.f, 0.f, 0.f, 0.f);
        frow<0, 1>(r[0], accT); frow<1, 1>(r[1], accT); frow<2, 1>(r[2], accT);
        frow<0, 1>(r[1], accB); frow<1, 1>(r[2], accB); frow<2, 1>(r[3], accB);
        float C2 = fmaf(0.5f * beta, (float)SUMB_D, K0C);
        float h = 0.5f * a2;
        *(float4*)(bo + (size_t)y0 * WW + c0) = make_float4(
            fmaf(h, accT.x, C2), fmaf(h, accT.y, C2),
            fmaf(h, accT.z, C2), fmaf(h, accT.w, C2));
        *(float4*)(bo + (size_t)(y0 + 1) * WW + c0) = make_float4(
            fmaf(h, accB.x, C2), fmaf(h, accB.y, C2),
            fmaf(h, accB.z, C2), fmaf(h, accB.w, C2));
    } else {
#pragma unroll
        for (int rr = 0; rr < 2; rr++) {
            int y = y0 + rr;
#pragma unroll
            for (int i = 0; i < 4; i++) {
                int gx = c0 + i;
                float acc = 0.f;
#define T(dy, dx, w)                                                   \
                {                                                      \
                    int yy = y + (dy), xx = gx + (dx);                 \
                    if ((unsigned)yy < HH && (unsigned)xx < WW) {      \
                        float xv = __ldg(xi + (size_t)yy * WW + xx);   \
                        acc = fmaf(fmaf(xv, a2, beta), (w), acc);      \
                    }                                                  \
                }
                T(-1, -1, B00) T(-1, 0, B01) T(-1, 1, B02)
                T( 0, -1, B10) T( 0, 0, B11) T( 0, 1, B12)
                T( 1, -1, B20) T( 1, 0, B21) T( 1, 1, B22)
#undef T
                bo[(size_t)y * WW + gx] = fmaf(acc, 0.5f, K0C);
            }
        }
    }
}

// Smem row fetch: one aligned LDS.128 + shuffles + boundary-lane patches.
__device__ __forceinline__ R6 ldrow(const float* p, int lane) {
    float4 m = *(const float4*)(p + 1);
    float lo = __shfl_up_sync(0xFFFFFFFFu, m.w, 1);
    float hi = __shfl_down_sync(0xFFFFFFFFu, m.x, 1);
    if (lane == 0)  lo = p[0];
    if (lane == 31) hi = p[5];
    R6 r; r.v0 = lo; r.v1 = m.x; r.v2 = m.y; r.v3 = m.z; r.v4 = m.w; r.v5 = hi;
    return r;
}

// A is already saturated (frowZsat); edge tiles force padding value 0.5.
template <bool EDGE>
__device__ __forceinline__ void emit4(float* q, const float4& A, bool yok,
                                      bool x0, bool x1, bool x2, bool x3) {
    float4 o;
    if (EDGE) {
        o.x = (yok && x0) ? A.x : 0.5f;
        o.y = (yok && x1) ? A.y : 0.5f;
        o.z = (yok && x2) ? A.z : 0.5f;
        o.w = (yok && x3) ? A.w : 0.5f;
    } else {
        o = A;
    }
    *(float4*)q = o;
}

// Direct-to-global store of a final-step row (central window [7,122] x [7,90]).
// Interior: lanes 2..29 full quad (2x STG.64, 8B-aligned: gxb = 2 mod 4 floats);
// lane 1 stores logical cols 7,8 (A.z,A.w); lane 30 stores 121,122 (A.x,A.y).
__device__ __forceinline__ void stg_int(float* dst, int gy, int gxb,
                                        const float4& A, int lane) {
    float* p = dst + (size_t)gy * WW + gxb;
    if (lane >= 2 && lane <= 29) {
        *(float2*)p       = make_float2(A.x, A.y);
        *(float2*)(p + 2) = make_float2(A.z, A.w);
    } else if (lane == 1) {
        *(float2*)(p + 2) = make_float2(A.z, A.w);
    } else if (lane == 30) {
        *(float2*)p       = make_float2(A.x, A.y);
    }
}
__device__ __forceinline__ void stg_edge(float* dst, int gy, int gx0, int xb,
                                         const float4& A) {
    if ((unsigned)gy >= HH) return;
    float* row = dst + (size_t)gy * WW;
    const float v[4] = {A.x, A.y, A.z, A.w};
#pragma unroll
    for (int i = 0; i < 4; i++) {
        int col = xb + 1 + i;
        int gx = gx0 + col;
        if (col >= 7 && col <= 122 && (unsigned)gx < WW) row[gx] = v[i];
    }
}

// Software-pipelined single smem step, 6 output rows per warp (8 row reads).
template <bool EDGE>
__device__ __forceinline__ float* do_steps(int nstep, float* a, float* b,
                                           const float4* BU, int lane,
                                           int o0, int xb, int gy0,
                                           bool x0, bool x1, bool x2, bool x3) {
#pragma unroll 1
    for (int t = 0; t < nstep; t++) {
        const float* ip = a + (o0 - 1) * SPW + xb + 3;
        float* op = b + o0 * SPW + xb + 4;
        float4 A0, A1, A2;
        R6 cur, nxt;
        cur = ldrow(ip, lane); ip += SPW;
        nxt = ldrow(ip, lane); ip += SPW;
        A0 = BU[0]; frow<0, 0>(cur, A0);
        cur = nxt;
        nxt = ldrow(ip, lane); ip += SPW;
        A1 = BU[1]; frow<1, 0>(cur, A0); frow<0, 0>(cur, A1);
#pragma unroll
        for (int k = 0; k < 4; k++) {
            cur = nxt;
            nxt = ldrow(ip, lane); ip += SPW;
            A2 = BU[2 + k];
            frowZsat(cur, A0);
            emit4<EDGE>(op + k * SPW, A0,
                        EDGE ? ((unsigned)(gy0 + o0 + k) < HH) : true,
                        x0, x1, x2, x3);
            frow<1, 0>(cur, A1); frow<0, 0>(cur, A2);
            A0 = A1; A1 = A2;
        }
        cur = nxt;
        nxt = ldrow(ip, lane);
        frowZsat(cur, A0);
        emit4<EDGE>(op + 4 * SPW, A0,
                    EDGE ? ((unsigned)(gy0 + o0 + 4) < HH) : true, x0, x1, x2, x3);
        frow<1, 0>(cur, A1);
        frowZsat(nxt, A1);
        emit4<EDGE>(op + 5 * SPW, A1,
                    EDGE ? ((unsigned)(gy0 + o0 + 5) < HH) : true, x0, x1, x2, x3);
        __syncthreads();
        float* tmp = a; a = b; b = tmp;
    }
    return a;   // buffer holding latest state
}

// Final step: compute 6 rows and store directly to global (no smem write).
// Only warps 1..NW-2 carry central rows (7..90); warps 0/15 have nothing to store.
template <bool EDGE>
__device__ __forceinline__ void do_final(const float* a, float* dst,
                                         const float4* BU, int lane, int wrp,
                                         int o0, int xb, int gx0, int gy0) {
    if (wrp == 0 || wrp == NW - 1) return;
    const int gxb = gx0 + xb + 1;
    const float* ip = a + (o0 - 1) * SPW + xb + 3;
    float4 A0, A1, A2;
    R6 cur, nxt;
    cur = ldrow(ip, lane); ip += SPW;
    nxt = ldrow(ip, lane); ip += SPW;
    A0 = BU[0]; frow<0, 0>(cur, A0);
    cur = nxt;
    nxt = ldrow(ip, lane); ip += SPW;
    A1 = BU[1]; frow<1, 0>(cur, A0); frow<0, 0>(cur, A1);
#pragma unroll
    for (int k = 0; k < 4; k++) {
        cur = nxt;
        nxt = ldrow(ip, lane); ip += SPW;
        A2 = BU[2 + k];
        frowZsat(cur, A0);
        if (EDGE) stg_edge(dst, gy0 + o0 + k, gx0, xb, A0);
        else      stg_int(dst, gy0 + o0 + k, gxb, A0, lane);
        frow<1, 0>(cur, A1); frow<0, 0>(cur, A2);
        A0 = A1; A1 = A2;
    }
    cur = nxt;
    nxt = ldrow(ip, lane);
    frowZsat(cur, A0);
    if (EDGE) stg_edge(dst, gy0 + o0 + 4, gx0, xb, A0);
    else      stg_int(dst, gy0 + o0 + 4, gxb, A0, lane);
    frow<1, 0>(cur, A1);
    frowZsat(nxt, A1);
    if (EDGE) stg_edge(dst, gy0 + o0 + 5, gx0, xb, A1);
    else      stg_int(dst, gy0 + o0 + 5, gxb, A1, lane);
}

// PASS 0: u1 analytic -> 5 smem steps + 1 STG step -> g_sA (u7)
// PASS 1: g_sA -> 6 smem + 1 STG -> g_sB (u14)
// PASS 2: g_sB -> 6 smem + 1 STG -> out  (u21)
template <int PASS>
__global__ void __launch_bounds__(NTH, 2) k_steps(float* __restrict__ out) {
    extern __shared__ float sm[];
    float* sA = sm;
    float* sB = sm + RH * SPW;
    const int tid = threadIdx.x, lane = tid & 31, wrp = tid >> 5;
    const int bx = blockIdx.x, by = blockIdx.y, img = blockIdx.z;
    const int gx0 = bx * TOX - 7, gy0 = by * TOY - 7;
    const bool edge = (bx == 0) | (bx == GX - 1) | (by == 0) | (by == GY - 1);

    const int o0 = 1 + RPW * wrp;   // update rows o0..o0+5 (1..96)
    const int xb = 4 * lane;        // update logical cols xb+1..xb+4 (1..128)
    const float* bsrc = g_bu2 + (size_t)img * HW;

    // ---- BU2 into registers (rows o0..o0+5) ----
    float4 BU[RPW];
    if (!edge) {
#pragma unroll
        for (int j = 0; j < RPW; j++) {
            const float2* p = (const float2*)(bsrc +
                (size_t)(gy0 + o0 + j) * WW + (gx0 + 1 + xb));
            float2 u = __ldg(p), v = __ldg(p + 1);
            BU[j] = make_float4(u.x, u.y, v.x, v.y);
        }
    } else {
#pragma unroll
        for (int j = 0; j < RPW; j++) {
            int gy = gy0 + o0 + j;
            float vv[4];
#pragma unroll
            for (int i = 0; i < 4; i++) {
                int gx = gx0 + 1 + xb + i;
                vv[i] = ((unsigned)gy < HH && (unsigned)gx < WW)
                          ? __ldg(bsrc + (size_t)gy * WW + gx) : 0.f;
            }
            BU[j] = make_float4(vv[0], vv[1], vv[2], vv[3]);
        }
    }

    // ---- source region into sA ----
    if (PASS == 0) {
        if (!edge) {
            for (int r = wrp; r < RH; r += NW) {
                const float* gp = bsrc + (size_t)(gy0 + r) * WW + gx0;
                float* sp = sA + r * SPW + 3;
                int c1 = 1 + 2 * lane, c2 = 65 + 2 * lane;
                float2 u = *(const float2*)(gp + c1);
                float2 v = *(const float2*)(gp + c2);
                u.x = __saturatef(S2K + u.x); u.y = __saturatef(S2K + u.y);
                v.x = __saturatef(S2K + v.x); v.y = __saturatef(S2K + v.y);
                *(float2*)(sp + c1) = u;
                *(float2*)(sp + c2) = v;
                if (lane == 0) {
                    sp[0]   = __saturatef(S2K + gp[0]);
                    sp[129] = __saturatef(S2K + gp[129]);
                }
            }
        } else {
            for (int r = wrp; r < RH; r += NW) {
                int gy = gy0 + r;
                bool yok = (unsigned)gy < HH;
                float* sp = sA + r * SPW + 3;
                for (int c = lane; c < RW; c += 32) {
                    int gx = gx0 + c;
                    sp[c] = (yok && (unsigned)gx < WW)
                              ? __saturatef(S2K + __ldg(bsrc + (size_t)gy * WW + gx))
                              : 0.5f;
                }
            }
        }
    } else {
        const float* src = (PASS == 1 ? g_sA : g_sB) + (size_t)img * HW;
        if (!edge) {
            for (int r = wrp; r < RH; r += NW) {
                const float* gp = src + (size_t)(gy0 + r) * WW + gx0;
                float* sp = sA + r * SPW + 3;
                int c1 = 1 + 2 * lane, c2 = 65 + 2 * lane;
                *(float2*)(sp + c1) = *(const float2*)(gp + c1);
                *(float2*)(sp + c2) = *(const float2*)(gp + c2);
                if (lane == 0) {
                    sp[0]   = gp[0];
                    sp[129] = gp[129];
                }
            }
        } else {
            for (int r = wrp; r < RH; r += NW) {
                int gy = gy0 + r;
                bool yok = (unsigned)gy < HH;
                float* sp = sA + r * SPW + 3;
                for (int c = lane; c < RW; c += 32) {
                    int gx = gx0 + c;
                    sp[c] = (yok && (unsigned)gx < WW)
                              ? __ldg(src + (size_t)gy * WW + gx) : 0.5f;
                }
            }
        }
    }
    __syncthreads();

    const bool x0 = (unsigned)(gx0 + xb + 1) < WW;
    const bool x1 = (unsigned)(gx0 + xb + 2) < WW;
    const bool x2 = (unsigned)(gx0 + xb + 3) < WW;
    const bool x3 = (unsigned)(gx0 + xb + 4) < WW;

    const int nsm = (PASS == 0) ? 5 : 6;   // smem steps; +1 STG step below
    float* fin = edge
        ? do_steps<true >(nsm, sA, sB, BU, lane, o0, xb, gy0, x0, x1, x2, x3)
        : do_steps<false>(nsm, sA, sB, BU, lane, o0, xb, gy0, true, true, true, true);

    float* dst = (PASS == 0 ? g_sA : PASS == 1 ? g_sB : out) + (size_t)img * HW;
    if (edge) do_final<true >(fin, dst, BU, lane, wrp, o0, xb, gx0, gy0);
    else      do_final<false>(fin, dst, BU, lane, wrp, o0, xb, gx0, gy0);
}

extern "C" void kernel_launch(void* const* d_in, const int* in_sizes, int n_in,
                              void* d_out, int out_size) {
    const float* x = (const float*)d_in[0];
    float* out = (float*)d_out;

    cudaFuncSetAttribute(k_steps<0>, cudaFuncAttributeMaxDynamicSharedMemorySize, SMEMB);
    cudaFuncSetAttribute(k_steps<1>, cudaFuncAttributeMaxDynamicSharedMemorySize, SMEMB);
    cudaFuncSetAttribute(k_steps<2>, cudaFuncAttributeMaxDynamicSharedMemorySize, SMEMB);

    k_init<<<1, 1>>>();
    k_minmax<<<2048, 256>>>((const float4*)x, (NB * HW) / 4);
    k_bu<<<dim3(1, HH / 2, NB), 256>>>(x);

    dim3 g(GX, GY, NB);
    k_steps<0><<<g, NTH, SMEMB>>>(out);
    k_steps<1><<<g, NTH, SMEMB>>>(out);
    k_steps<2><<<g, NTH, SMEMB>>>(out);
}